// round 2
// baseline (speedup 1.0000x reference)
#include <cuda_runtime.h>
#include <cuda_bf16.h>
#include <cstdint>

#define NN 131072
#define EE 2097152
#define GG 512

// -------------------- device scratch (no allocations allowed) --------------------
__device__ float g_XA[(size_t)NN * 128];
__device__ float g_XB[(size_t)NN * 128];
__device__ float g_PA[(size_t)NN * 128];
__device__ float g_PB[(size_t)NN * 128];
__device__ float g_dis[NN];          // deg during prep, then rsqrt(deg)
__device__ int   g_src[EE];
__device__ int   g_dst[EE];
__device__ float g_w2[EE];           // dis[src]*dis[dst]
__device__ unsigned g_pool[GG * 128];

// -------------------- helpers --------------------
__device__ __forceinline__ void red_add_v4(float* p, float4 v) {
    asm volatile("red.global.add.v4.f32 [%0], {%1,%2,%3,%4};"
                 :: "l"(p), "f"(v.x), "f"(v.y), "f"(v.z), "f"(v.w) : "memory");
}
__device__ __forceinline__ void red_add_v2(float* p, float2 v) {
    asm volatile("red.global.add.v2.f32 [%0], {%1,%2};"
                 :: "l"(p), "f"(v.x), "f"(v.y) : "memory");
}

static inline int cdiv(long long a, int b) { return (int)((a + b - 1) / b); }

// -------------------- prep kernels --------------------
__global__ void prep_init_k() {
    int n = blockIdx.x * blockDim.x + threadIdx.x;
    if (n < NN) g_dis[n] = 1.0f;             // deg starts at 1 (self loop)
    if (n < GG * 128) g_pool[n] = 0u;        // pool init (relu outputs >= 0)
}

__global__ void prep_edge_k(const int* __restrict__ ei) {
    int e = blockIdx.x * blockDim.x + threadIdx.x;
    if (e >= EE) return;
    int s = ei[e];
    int d = ei[EE + e];
    g_src[e] = s;
    g_dst[e] = d;
    atomicAdd(&g_dis[d], 1.0f);
}

__global__ void prep_dis_k(const float* __restrict__ x) {
    int n = blockIdx.x * blockDim.x + threadIdx.x;
    if (n >= NN) return;
    float dv = rsqrtf(g_dis[n]);
    g_dis[n] = dv;
    float d2 = dv * dv;
    // init P for layer 1 (fin=2): self-loop term d^-1 * x
    g_PA[2 * n]     = d2 * x[2 * n];
    g_PA[2 * n + 1] = d2 * x[2 * n + 1];
}

__global__ void prep_w_k() {
    int e = blockIdx.x * blockDim.x + threadIdx.x;
    if (e >= EE) return;
    g_w2[e] = g_dis[g_src[e]] * g_dis[g_dst[e]];
}

// -------------------- scatter: P[dst] += w * X[src]  (fin channels) --------------------
__global__ void scatter2_k(const float* __restrict__ X, float* __restrict__ P) {
    int e = blockIdx.x * blockDim.x + threadIdx.x;
    if (e >= EE) return;
    int s = g_src[e], d = g_dst[e];
    float w = g_w2[e];
    float2 v = __ldg((const float2*)(X + (size_t)s * 2));
    v.x *= w; v.y *= w;
    red_add_v2(P + (size_t)d * 2, v);
}

template<int FIN>
__global__ void scatter_k(const float* __restrict__ X, float* __restrict__ P) {
    constexpr int TPE = FIN / 4;
    long long t = (long long)blockIdx.x * blockDim.x + threadIdx.x;
    int e = (int)(t / TPE);
    int lane = (int)(t % TPE);
    if (e >= EE) return;
    int s = g_src[e], d = g_dst[e];
    float w = g_w2[e];
    int c = lane * 4;
    float4 v = __ldg((const float4*)(X + (size_t)s * FIN + c));
    v.x *= w; v.y *= w; v.z *= w; v.w *= w;
    red_add_v4(P + (size_t)d * FIN + c, v);
}

// -------------------- fused GEMM + bias + relu + next-P init --------------------
// Xo = relu(P @ W + b);  if WP:  Po = (dis^2) * Xo
template<int FIN, int FOUT, bool WP>
__global__ void gemm_k(const float* __restrict__ P, const float* __restrict__ W,
                       const float* __restrict__ B, float* __restrict__ Xo,
                       float* __restrict__ Po) {
    constexpr int TPR = FOUT / 4;                 // col-groups per row
    int t = blockIdx.x * blockDim.x + threadIdx.x;
    int rg = t / TPR;
    int c = (t % TPR) * 4;
    int r0 = rg * 4;
    if (r0 >= NN) return;

    float4 a0 = {0,0,0,0}, a1 = {0,0,0,0}, a2 = {0,0,0,0}, a3 = {0,0,0,0};
    const float* p0 = P + (size_t)r0 * FIN;
    const float* p1 = p0 + FIN;
    const float* p2 = p1 + FIN;
    const float* p3 = p2 + FIN;

    #pragma unroll 8
    for (int k = 0; k < FIN; k++) {
        float4 wv = __ldg((const float4*)(W + (size_t)k * FOUT + c));
        float x0 = __ldg(p0 + k);
        float x1 = __ldg(p1 + k);
        float x2 = __ldg(p2 + k);
        float x3 = __ldg(p3 + k);
        a0.x += x0 * wv.x; a0.y += x0 * wv.y; a0.z += x0 * wv.z; a0.w += x0 * wv.w;
        a1.x += x1 * wv.x; a1.y += x1 * wv.y; a1.z += x1 * wv.z; a1.w += x1 * wv.w;
        a2.x += x2 * wv.x; a2.y += x2 * wv.y; a2.z += x2 * wv.z; a2.w += x2 * wv.w;
        a3.x += x3 * wv.x; a3.y += x3 * wv.y; a3.z += x3 * wv.z; a3.w += x3 * wv.w;
    }

    float4 bv = __ldg((const float4*)(B + c));

    #pragma unroll
    for (int j = 0; j < 4; j++) {
        float4 a = (j == 0) ? a0 : (j == 1) ? a1 : (j == 2) ? a2 : a3;
        float4 o;
        o.x = fmaxf(a.x + bv.x, 0.f);
        o.y = fmaxf(a.y + bv.y, 0.f);
        o.z = fmaxf(a.z + bv.z, 0.f);
        o.w = fmaxf(a.w + bv.w, 0.f);
        *(float4*)(Xo + (size_t)(r0 + j) * FOUT + c) = o;
        if (WP) {
            float dr = g_dis[r0 + j];
            float d2 = dr * dr;
            float4 q = { o.x * d2, o.y * d2, o.z * d2, o.w * d2 };
            *(float4*)(Po + (size_t)(r0 + j) * FOUT + c) = q;
        }
    }
}

// -------------------- pooling: segment max over batch --------------------
__global__ void pool_k(const float* __restrict__ X, const int* __restrict__ batch) {
    int t = blockIdx.x * blockDim.x + threadIdx.x;
    int n = t >> 5;
    int lane = t & 31;
    if (n >= NN) return;
    int b = batch[n];
    int c = lane * 4;
    float4 v = *(const float4*)(X + (size_t)n * 128 + c);
    unsigned* gp = g_pool + (size_t)b * 128 + c;
    atomicMax(gp + 0, __float_as_uint(v.x));   // valid: all values >= 0 after relu
    atomicMax(gp + 1, __float_as_uint(v.y));
    atomicMax(gp + 2, __float_as_uint(v.z));
    atomicMax(gp + 3, __float_as_uint(v.w));
}

// -------------------- MLP head: relu(g@Wl1+bl1)@Wl2+bl2 --------------------
__global__ void mlp_k(const float* __restrict__ Wl1, const float* __restrict__ bl1,
                      const float* __restrict__ Wl2, const float* __restrict__ bl2,
                      float* __restrict__ out) {
    __shared__ float gr[128];
    __shared__ float hid[64];
    int g = blockIdx.x;
    int t = threadIdx.x;   // 64 threads
    gr[t]      = __uint_as_float(g_pool[(size_t)g * 128 + t]);
    gr[t + 64] = __uint_as_float(g_pool[(size_t)g * 128 + t + 64]);
    __syncthreads();
    float a = bl1[t];
    #pragma unroll 8
    for (int k = 0; k < 128; k++) a += gr[k] * Wl1[(size_t)k * 64 + t];
    hid[t] = fmaxf(a, 0.f);
    __syncthreads();
    if (t < 10) {
        float o = bl2[t];
        #pragma unroll 8
        for (int j = 0; j < 64; j++) o += hid[j] * Wl2[(size_t)j * 10 + t];
        out[(size_t)g * 10 + t] = o;
    }
}

// -------------------- host launcher --------------------
extern "C" void kernel_launch(void* const* d_in, const int* in_sizes, int n_in,
                              void* d_out, int out_size) {
    const float* x     = (const float*)d_in[0];
    const int*   ei    = (const int*)d_in[1];     // int32 (JAX x64 disabled)
    const int*   batch = (const int*)d_in[2];     // int32
    const float* W[6], *b[6];
    for (int i = 0; i < 6; i++) {
        W[i] = (const float*)d_in[3 + 2 * i];
        b[i] = (const float*)d_in[4 + 2 * i];
    }
    const float* Wl1 = (const float*)d_in[15];
    const float* bl1 = (const float*)d_in[16];
    const float* Wl2 = (const float*)d_in[17];
    const float* bl2 = (const float*)d_in[18];
    float* out = (float*)d_out;

    float *XA, *XB, *PA, *PB;
    cudaGetSymbolAddress((void**)&XA, g_XA);
    cudaGetSymbolAddress((void**)&XB, g_XB);
    cudaGetSymbolAddress((void**)&PA, g_PA);
    cudaGetSymbolAddress((void**)&PB, g_PB);

    const int T = 256;

    // prep
    prep_init_k<<<cdiv(NN, T), T>>>();
    prep_edge_k<<<cdiv(EE, T), T>>>(ei);
    prep_dis_k<<<cdiv(NN, T), T>>>(x);
    prep_w_k<<<cdiv(EE, T), T>>>();

    // layer 1: fin=2 -> fout=16   (P in PA, out X->XA, next P->PB)
    scatter2_k<<<cdiv(EE, T), T>>>(x, PA);
    gemm_k<2, 16, true><<<cdiv((long long)(NN / 4) * (16 / 4), T), T>>>(PA, W[0], b[0], XA, PB);

    // layer 2: fin=16 -> fout=32
    scatter_k<16><<<cdiv((long long)EE * 4, T), T>>>(XA, PB);
    gemm_k<16, 32, true><<<cdiv((long long)(NN / 4) * (32 / 4), T), T>>>(PB, W[1], b[1], XB, PA);

    // layer 3: fin=32 -> fout=48
    scatter_k<32><<<cdiv((long long)EE * 8, T), T>>>(XB, PA);
    gemm_k<32, 48, true><<<cdiv((long long)(NN / 4) * (48 / 4), T), T>>>(PA, W[2], b[2], XA, PB);

    // layer 4: fin=48 -> fout=64
    scatter_k<48><<<cdiv((long long)EE * 12, T), T>>>(XA, PB);
    gemm_k<48, 64, true><<<cdiv((long long)(NN / 4) * (64 / 4), T), T>>>(PB, W[3], b[3], XB, PA);

    // layer 5: fin=64 -> fout=96
    scatter_k<64><<<cdiv((long long)EE * 16, T), T>>>(XB, PA);
    gemm_k<64, 96, true><<<cdiv((long long)(NN / 4) * (96 / 4), T), T>>>(PA, W[4], b[4], XA, PB);

    // layer 6: fin=96 -> fout=128 (last: no next-P)
    scatter_k<96><<<cdiv((long long)EE * 24, T), T>>>(XA, PB);
    gemm_k<96, 128, false><<<cdiv((long long)(NN / 4) * (128 / 4), T), T>>>(PB, W[5], b[5], XB, nullptr);

    // pool + head
    pool_k<<<cdiv((long long)NN * 32, T), T>>>(XB, batch);
    mlp_k<<<GG, 64>>>(Wl1, bl1, Wl2, bl2, out);
}

// round 4
// speedup vs baseline: 1.4819x; 1.4819x over previous
#include <cuda_runtime.h>
#include <cuda_bf16.h>
#include <cstdint>

#define NN 131072
#define EE 2097152
#define GG 512
#define NBLK 128          // scan blocks: 128 * 1024 = NN

// -------------------- device scratch (no allocations allowed) --------------------
__device__ float g_YA[(size_t)NN * 128];
__device__ float g_YB[(size_t)NN * 128];
__device__ float g_P [(size_t)NN * 128];
__device__ float g_dis[NN];
__device__ int   g_cnt[NN];          // degree histogram, then placement cursor
__device__ int   g_rowptr[NN + 1];
__device__ int   g_bsum[NBLK];
__device__ int   g_col[EE];          // CSR column (src) sorted by dst
__device__ unsigned g_pool[GG * 128];

static inline int cdiv(long long a, int b) { return (int)((a + b - 1) / b); }

// ==================== CSR build ====================
__global__ void prep_init_k() {
    int n = blockIdx.x * blockDim.x + threadIdx.x;
    if (n < NN) g_cnt[n] = 0;
    if (n < GG * 128) g_pool[n] = 0u;        // relu outputs >= 0
}

__global__ void hist_k(const int* __restrict__ ei) {
    int e = blockIdx.x * blockDim.x + threadIdx.x;
    if (e >= EE) return;
    atomicAdd(&g_cnt[ei[EE + e]], 1);
}

// block-local exclusive scan of g_cnt (1024/block), block totals -> g_bsum
__global__ void scan_a_k() {
    __shared__ int wsum[32];
    int n = blockIdx.x * 1024 + threadIdx.x;
    int lane = threadIdx.x & 31, wid = threadIdx.x >> 5;
    int v = g_cnt[n];
    int x = v;
    #pragma unroll
    for (int o = 1; o < 32; o <<= 1) { int y = __shfl_up_sync(~0u, x, o); if (lane >= o) x += y; }
    if (lane == 31) wsum[wid] = x;
    __syncthreads();
    if (wid == 0) {
        int s = wsum[lane];
        #pragma unroll
        for (int o = 1; o < 32; o <<= 1) { int y = __shfl_up_sync(~0u, s, o); if (lane >= o) s += y; }
        wsum[lane] = s;
    }
    __syncthreads();
    int excl = x - v + (wid > 0 ? wsum[wid - 1] : 0);
    g_rowptr[n] = excl;
    if (threadIdx.x == 1023) g_bsum[blockIdx.x] = excl + v;
}

// exclusive scan of the 128 block totals (one warp, 4 per lane)
__global__ void scan_b_k() {
    int lane = threadIdx.x;          // 32 threads
    int v[4], tot = 0;
    #pragma unroll
    for (int i = 0; i < 4; i++) { v[i] = g_bsum[lane * 4 + i]; tot += v[i]; }
    int x = tot;
    #pragma unroll
    for (int o = 1; o < 32; o <<= 1) { int y = __shfl_up_sync(~0u, x, o); if (lane >= o) x += y; }
    int excl = x - tot;
    #pragma unroll
    for (int i = 0; i < 4; i++) { g_bsum[lane * 4 + i] = excl; excl += v[i]; }
}

// finalize rowptr, compute dis = rsqrt(deg+1), init Y0 = dis * x, zero cursor
__global__ void scan_c_k(const float* __restrict__ x) {
    int n = blockIdx.x * blockDim.x + threadIdx.x;
    if (n >= NN) return;
    g_rowptr[n] += g_bsum[n >> 10];
    float dv = rsqrtf((float)g_cnt[n] + 1.0f);
    g_dis[n] = dv;
    g_cnt[n] = 0;                     // becomes placement cursor
    g_YA[2 * n]     = dv * x[2 * n];
    g_YA[2 * n + 1] = dv * x[2 * n + 1];
    if (n == 0) g_rowptr[NN] = EE;
}

__global__ void place_k(const int* __restrict__ ei) {
    int e = blockIdx.x * blockDim.x + threadIdx.x;
    if (e >= EE) return;
    int s = ei[e];
    int d = ei[EE + e];
    int p = atomicAdd(&g_cnt[d], 1);
    g_col[g_rowptr[d] + p] = s;
}

// ==================== aggregation: P_i = dis_i * (Y_i + sum_{j in N(i)} Y_j) ====================
template<int FIN>
__global__ void agg_k(const float* __restrict__ Y, float* __restrict__ P) {
    constexpr int G = FIN / 4;        // threads per node
    long long t = (long long)blockIdx.x * blockDim.x + threadIdx.x;
    int node = (int)(t / G);
    int c = (int)(t % G) * 4;
    if (node >= NN) return;
    int beg = g_rowptr[node], end = g_rowptr[node + 1];
    float4 acc = *(const float4*)(Y + (size_t)node * FIN + c);   // self term
    int i = beg;
    for (; i + 4 <= end; i += 4) {
        int j0 = g_col[i], j1 = g_col[i + 1], j2 = g_col[i + 2], j3 = g_col[i + 3];
        float4 v0 = __ldg((const float4*)(Y + (size_t)j0 * FIN + c));
        float4 v1 = __ldg((const float4*)(Y + (size_t)j1 * FIN + c));
        float4 v2 = __ldg((const float4*)(Y + (size_t)j2 * FIN + c));
        float4 v3 = __ldg((const float4*)(Y + (size_t)j3 * FIN + c));
        acc.x += (v0.x + v1.x) + (v2.x + v3.x);
        acc.y += (v0.y + v1.y) + (v2.y + v3.y);
        acc.z += (v0.z + v1.z) + (v2.z + v3.z);
        acc.w += (v0.w + v1.w) + (v2.w + v3.w);
    }
    for (; i < end; i++) {
        int j = g_col[i];
        float4 v = __ldg((const float4*)(Y + (size_t)j * FIN + c));
        acc.x += v.x; acc.y += v.y; acc.z += v.z; acc.w += v.w;
    }
    float s = g_dis[node];
    acc.x *= s; acc.y *= s; acc.z *= s; acc.w *= s;
    *(float4*)(P + (size_t)node * FIN + c) = acc;
}

// FIN=2 special case: one thread per node, float2
__global__ void agg2_k(const float* __restrict__ Y, float* __restrict__ P) {
    int node = blockIdx.x * blockDim.x + threadIdx.x;
    if (node >= NN) return;
    int beg = g_rowptr[node], end = g_rowptr[node + 1];
    float2 acc = *(const float2*)(Y + (size_t)node * 2);
    int i = beg;
    for (; i + 4 <= end; i += 4) {
        int j0 = g_col[i], j1 = g_col[i + 1], j2 = g_col[i + 2], j3 = g_col[i + 3];
        float2 v0 = __ldg((const float2*)(Y + (size_t)j0 * 2));
        float2 v1 = __ldg((const float2*)(Y + (size_t)j1 * 2));
        float2 v2 = __ldg((const float2*)(Y + (size_t)j2 * 2));
        float2 v3 = __ldg((const float2*)(Y + (size_t)j3 * 2));
        acc.x += (v0.x + v1.x) + (v2.x + v3.x);
        acc.y += (v0.y + v1.y) + (v2.y + v3.y);
    }
    for (; i < end; i++) {
        int j = g_col[i];
        float2 v = __ldg((const float2*)(Y + (size_t)j * 2));
        acc.x += v.x; acc.y += v.y;
    }
    float s = g_dis[node];
    acc.x *= s; acc.y *= s;
    *(float2*)(P + (size_t)node * 2) = acc;
}

// ==================== GEMM + bias + relu (+ dis scaling for next layer's Y) ====================
template<int FIN, int FOUT, bool SCALE>
__global__ void gemm_k(const float* __restrict__ P, const float* __restrict__ W,
                       const float* __restrict__ B, float* __restrict__ Yo) {
    constexpr int TPR = FOUT / 4;
    int t = blockIdx.x * blockDim.x + threadIdx.x;
    int rg = t / TPR;
    int c = (t % TPR) * 4;
    int r0 = rg * 4;
    if (r0 >= NN) return;

    float4 a0 = {0,0,0,0}, a1 = {0,0,0,0}, a2 = {0,0,0,0}, a3 = {0,0,0,0};
    const float* p0 = P + (size_t)r0 * FIN;
    const float* p1 = p0 + FIN;
    const float* p2 = p1 + FIN;
    const float* p3 = p2 + FIN;

    #pragma unroll 8
    for (int k = 0; k < FIN; k++) {
        float4 wv = __ldg((const float4*)(W + (size_t)k * FOUT + c));
        float x0 = __ldg(p0 + k);
        float x1 = __ldg(p1 + k);
        float x2 = __ldg(p2 + k);
        float x3 = __ldg(p3 + k);
        a0.x += x0 * wv.x; a0.y += x0 * wv.y; a0.z += x0 * wv.z; a0.w += x0 * wv.w;
        a1.x += x1 * wv.x; a1.y += x1 * wv.y; a1.z += x1 * wv.z; a1.w += x1 * wv.w;
        a2.x += x2 * wv.x; a2.y += x2 * wv.y; a2.z += x2 * wv.z; a2.w += x2 * wv.w;
        a3.x += x3 * wv.x; a3.y += x3 * wv.y; a3.z += x3 * wv.z; a3.w += x3 * wv.w;
    }

    float4 bv = __ldg((const float4*)(B + c));

    #pragma unroll
    for (int j = 0; j < 4; j++) {
        float4 a = (j == 0) ? a0 : (j == 1) ? a1 : (j == 2) ? a2 : a3;
        float m = SCALE ? g_dis[r0 + j] : 1.0f;
        float4 o;
        o.x = m * fmaxf(a.x + bv.x, 0.f);
        o.y = m * fmaxf(a.y + bv.y, 0.f);
        o.z = m * fmaxf(a.z + bv.z, 0.f);
        o.w = m * fmaxf(a.w + bv.w, 0.f);
        *(float4*)(Yo + (size_t)(r0 + j) * FOUT + c) = o;
    }
}

// ==================== pooling + MLP head ====================
__global__ void pool_k(const float* __restrict__ X, const int* __restrict__ batch) {
    int t = blockIdx.x * blockDim.x + threadIdx.x;
    int n = t >> 5;
    int lane = t & 31;
    if (n >= NN) return;
    int b = batch[n];
    int c = lane * 4;
    float4 v = *(const float4*)(X + (size_t)n * 128 + c);
    unsigned* gp = g_pool + (size_t)b * 128 + c;
    atomicMax(gp + 0, __float_as_uint(v.x));
    atomicMax(gp + 1, __float_as_uint(v.y));
    atomicMax(gp + 2, __float_as_uint(v.z));
    atomicMax(gp + 3, __float_as_uint(v.w));
}

__global__ void mlp_k(const float* __restrict__ Wl1, const float* __restrict__ bl1,
                      const float* __restrict__ Wl2, const float* __restrict__ bl2,
                      float* __restrict__ out) {
    __shared__ float gr[128];
    __shared__ float hid[64];
    int g = blockIdx.x;
    int t = threadIdx.x;   // 64 threads
    gr[t]      = __uint_as_float(g_pool[(size_t)g * 128 + t]);
    gr[t + 64] = __uint_as_float(g_pool[(size_t)g * 128 + t + 64]);
    __syncthreads();
    float a = bl1[t];
    #pragma unroll 8
    for (int k = 0; k < 128; k++) a += gr[k] * Wl1[(size_t)k * 64 + t];
    hid[t] = fmaxf(a, 0.f);
    __syncthreads();
    if (t < 10) {
        float o = bl2[t];
        #pragma unroll 8
        for (int j = 0; j < 64; j++) o += hid[j] * Wl2[(size_t)j * 10 + t];
        out[(size_t)g * 10 + t] = o;
    }
}

// ==================== host launcher ====================
extern "C" void kernel_launch(void* const* d_in, const int* in_sizes, int n_in,
                              void* d_out, int out_size) {
    const float* x     = (const float*)d_in[0];
    const int*   ei    = (const int*)d_in[1];
    const int*   batch = (const int*)d_in[2];
    const float* W[6], *b[6];
    for (int i = 0; i < 6; i++) {
        W[i] = (const float*)d_in[3 + 2 * i];
        b[i] = (const float*)d_in[4 + 2 * i];
    }
    const float* Wl1 = (const float*)d_in[15];
    const float* bl1 = (const float*)d_in[16];
    const float* Wl2 = (const float*)d_in[17];
    const float* bl2 = (const float*)d_in[18];
    float* out = (float*)d_out;

    float *YA, *YB, *P;
    cudaGetSymbolAddress((void**)&YA, g_YA);
    cudaGetSymbolAddress((void**)&YB, g_YB);
    cudaGetSymbolAddress((void**)&P,  g_P);

    const int T = 256;

    // CSR build + normalization
    prep_init_k<<<cdiv(NN, T), T>>>();
    hist_k<<<cdiv(EE, T), T>>>(ei);
    scan_a_k<<<NBLK, 1024>>>();
    scan_b_k<<<1, 32>>>();
    scan_c_k<<<cdiv(NN, T), T>>>(x);
    place_k<<<cdiv(EE, T), T>>>(ei);

    // layer 1: fin=2 -> 16
    agg2_k<<<cdiv(NN, T), T>>>(YA, P);
    gemm_k<2, 16, true><<<cdiv((long long)(NN / 4) * 4, T), T>>>(P, W[0], b[0], YB);

    // layer 2: 16 -> 32
    agg_k<16><<<cdiv((long long)NN * 4, T), T>>>(YB, P);
    gemm_k<16, 32, true><<<cdiv((long long)(NN / 4) * 8, T), T>>>(P, W[1], b[1], YA);

    // layer 3: 32 -> 48
    agg_k<32><<<cdiv((long long)NN * 8, T), T>>>(YA, P);
    gemm_k<32, 48, true><<<cdiv((long long)(NN / 4) * 12, T), T>>>(P, W[2], b[2], YB);

    // layer 4: 48 -> 64
    agg_k<48><<<cdiv((long long)NN * 12, T), T>>>(YB, P);
    gemm_k<48, 64, true><<<cdiv((long long)(NN / 4) * 16, T), T>>>(P, W[3], b[3], YA);

    // layer 5: 64 -> 96
    agg_k<64><<<cdiv((long long)NN * 16, T), T>>>(YA, P);
    gemm_k<64, 96, true><<<cdiv((long long)(NN / 4) * 24, T), T>>>(P, W[4], b[4], YB);

    // layer 6: 96 -> 128 (no dis scaling: final node features)
    agg_k<96><<<cdiv((long long)NN * 24, T), T>>>(YB, P);
    gemm_k<96, 128, false><<<cdiv((long long)(NN / 4) * 32, T), T>>>(P, W[5], b[5], YA);

    // pool + head
    pool_k<<<cdiv((long long)NN * 32, T), T>>>(YA, batch);
    mlp_k<<<GG, 64>>>(Wl1, bl1, Wl2, bl2, out);
}

// round 5
// speedup vs baseline: 1.8859x; 1.2727x over previous
#include <cuda_runtime.h>
#include <cuda_bf16.h>
#include <cstdint>

#define NN 131072
#define EE 2097152
#define GG 512
#define NBLK 128          // scan blocks: 128 * 1024 = NN
#define DB 512            // degree-histogram bins
#define KP 16             // nodes per pool warp

// -------------------- device scratch (no allocations allowed) --------------------
__device__ float g_YA[(size_t)NN * 128];
__device__ float g_YB[(size_t)NN * 128];
__device__ float g_P [(size_t)NN * 128];
__device__ float g_dis[NN];
__device__ int   g_cnt[NN];          // degree histogram, then placement cursor
__device__ int   g_rowptr[NN + 1];
__device__ int   g_bsum[NBLK];
__device__ int   g_dhist[DB];        // degree histogram -> offsets -> cursors
__device__ int   g_perm[NN];         // nodes sorted by degree
__device__ int   g_col[EE];          // CSR column (src) sorted by dst
__device__ unsigned g_pool[GG * 128];

static inline int cdiv(long long a, int b) { return (int)((a + b - 1) / b); }

// ==================== CSR build + degree sort ====================
__global__ void prep_init_k() {
    int n = blockIdx.x * blockDim.x + threadIdx.x;
    if (n < NN) g_cnt[n] = 0;
    if (n < GG * 128) g_pool[n] = 0u;        // relu outputs >= 0
    if (n < DB) g_dhist[n] = 0;
}

__global__ void hist_k(const int* __restrict__ ei) {
    int e = blockIdx.x * blockDim.x + threadIdx.x;
    if (e >= EE) return;
    atomicAdd(&g_cnt[ei[EE + e]], 1);
}

// block-local exclusive scan of g_cnt (1024/block) -> rowptr partial, block totals -> g_bsum
// also: degree histogram for the counting sort
__global__ void scan_a_k() {
    __shared__ int wsum[32];
    int n = blockIdx.x * 1024 + threadIdx.x;
    int lane = threadIdx.x & 31, wid = threadIdx.x >> 5;
    int v = g_cnt[n];
    atomicAdd(&g_dhist[v < DB ? v : DB - 1], 1);
    int x = v;
    #pragma unroll
    for (int o = 1; o < 32; o <<= 1) { int y = __shfl_up_sync(~0u, x, o); if (lane >= o) x += y; }
    if (lane == 31) wsum[wid] = x;
    __syncthreads();
    if (wid == 0) {
        int s = wsum[lane];
        #pragma unroll
        for (int o = 1; o < 32; o <<= 1) { int y = __shfl_up_sync(~0u, s, o); if (lane >= o) s += y; }
        wsum[lane] = s;
    }
    __syncthreads();
    int excl = x - v + (wid > 0 ? wsum[wid - 1] : 0);
    g_rowptr[n] = excl;
    if (threadIdx.x == 1023) g_bsum[blockIdx.x] = excl + v;
}

__device__ __forceinline__ void scan_shared(int* sh, int n, int t) {
    for (int o = 1; o < n; o <<= 1) {
        int add = (t >= o && t < n) ? sh[t - o] : 0;
        __syncthreads();
        if (t < n) sh[t] += add;
        __syncthreads();
    }
}

// block 0: exclusive scan of g_bsum (NBLK);  block 1: exclusive scan of g_dhist (DB)
__global__ void scan_b2_k() {
    __shared__ int sh[DB];
    int t = threadIdx.x;               // 512 threads
    if (blockIdx.x == 0) {
        int v = (t < NBLK) ? g_bsum[t] : 0;
        if (t < NBLK) sh[t] = v;
        __syncthreads();
        scan_shared(sh, NBLK, t);
        if (t < NBLK) g_bsum[t] = sh[t] - v;     // exclusive
    } else {
        int v = g_dhist[t];
        sh[t] = v;
        __syncthreads();
        scan_shared(sh, DB, t);
        g_dhist[t] = sh[t] - v;                  // exclusive offsets (become cursors)
    }
}

// finalize rowptr, dis = rsqrt(deg+1), Y0 = dis*x, place node into degree-sorted perm
__global__ void scan_c_k(const float* __restrict__ x) {
    int n = blockIdx.x * blockDim.x + threadIdx.x;
    if (n >= NN) return;
    g_rowptr[n] += g_bsum[n >> 10];
    int deg = g_cnt[n];
    float dv = rsqrtf((float)deg + 1.0f);
    g_dis[n] = dv;
    int d = deg < DB ? deg : DB - 1;
    int p = atomicAdd(&g_dhist[d], 1);
    g_perm[p] = n;
    g_cnt[n] = 0;                     // becomes placement cursor
    g_YA[2 * n]     = dv * x[2 * n];
    g_YA[2 * n + 1] = dv * x[2 * n + 1];
    if (n == 0) g_rowptr[NN] = EE;
}

__global__ void place_k(const int* __restrict__ ei) {
    int e = blockIdx.x * blockDim.x + threadIdx.x;
    if (e >= EE) return;
    int s = ei[e];
    int d = ei[EE + e];
    int p = atomicAdd(&g_cnt[d], 1);
    g_col[g_rowptr[d] + p] = s;
}

// ==================== aggregation: P_i = dis_i * (Y_i + sum_{j in N(i)} Y_j) ====================
// degree-sorted node order -> uniform trip counts within a warp
template<int FIN>
__global__ void agg_k(const float* __restrict__ Y, float* __restrict__ P) {
    constexpr int G = FIN / 4;        // threads per node
    long long t = (long long)blockIdx.x * blockDim.x + threadIdx.x;
    int grp = (int)(t / G);
    int c = (int)(t % G) * 4;
    if (grp >= NN) return;
    int node = g_perm[grp];
    int beg = g_rowptr[node], end = g_rowptr[node + 1];
    float4 acc = *(const float4*)(Y + (size_t)node * FIN + c);   // self term
    int i = beg;
    for (; i + 4 <= end; i += 4) {
        int j0 = g_col[i], j1 = g_col[i + 1], j2 = g_col[i + 2], j3 = g_col[i + 3];
        float4 v0 = __ldg((const float4*)(Y + (size_t)j0 * FIN + c));
        float4 v1 = __ldg((const float4*)(Y + (size_t)j1 * FIN + c));
        float4 v2 = __ldg((const float4*)(Y + (size_t)j2 * FIN + c));
        float4 v3 = __ldg((const float4*)(Y + (size_t)j3 * FIN + c));
        acc.x += (v0.x + v1.x) + (v2.x + v3.x);
        acc.y += (v0.y + v1.y) + (v2.y + v3.y);
        acc.z += (v0.z + v1.z) + (v2.z + v3.z);
        acc.w += (v0.w + v1.w) + (v2.w + v3.w);
    }
    for (; i < end; i++) {
        int j = g_col[i];
        float4 v = __ldg((const float4*)(Y + (size_t)j * FIN + c));
        acc.x += v.x; acc.y += v.y; acc.z += v.z; acc.w += v.w;
    }
    float s = g_dis[node];
    acc.x *= s; acc.y *= s; acc.z *= s; acc.w *= s;
    *(float4*)(P + (size_t)node * FIN + c) = acc;
}

// FIN=2 special case: one thread per node, float2
__global__ void agg2_k(const float* __restrict__ Y, float* __restrict__ P) {
    int grp = blockIdx.x * blockDim.x + threadIdx.x;
    if (grp >= NN) return;
    int node = g_perm[grp];
    int beg = g_rowptr[node], end = g_rowptr[node + 1];
    float2 acc = *(const float2*)(Y + (size_t)node * 2);
    int i = beg;
    for (; i + 4 <= end; i += 4) {
        int j0 = g_col[i], j1 = g_col[i + 1], j2 = g_col[i + 2], j3 = g_col[i + 3];
        float2 v0 = __ldg((const float2*)(Y + (size_t)j0 * 2));
        float2 v1 = __ldg((const float2*)(Y + (size_t)j1 * 2));
        float2 v2 = __ldg((const float2*)(Y + (size_t)j2 * 2));
        float2 v3 = __ldg((const float2*)(Y + (size_t)j3 * 2));
        acc.x += (v0.x + v1.x) + (v2.x + v3.x);
        acc.y += (v0.y + v1.y) + (v2.y + v3.y);
    }
    for (; i < end; i++) {
        int j = g_col[i];
        float2 v = __ldg((const float2*)(Y + (size_t)j * 2));
        acc.x += v.x; acc.y += v.y;
    }
    float s = g_dis[node];
    acc.x *= s; acc.y *= s;
    *(float2*)(P + (size_t)node * 2) = acc;
}

// ==================== GEMM + bias + relu (+ dis scaling for next layer's Y) ====================
template<int FIN, int FOUT, bool SCALE>
__global__ void gemm_k(const float* __restrict__ P, const float* __restrict__ W,
                       const float* __restrict__ B, float* __restrict__ Yo) {
    constexpr int TPR = FOUT / 4;
    int t = blockIdx.x * blockDim.x + threadIdx.x;
    int rg = t / TPR;
    int c = (t % TPR) * 4;
    int r0 = rg * 4;
    if (r0 >= NN) return;

    float4 a0 = {0,0,0,0}, a1 = {0,0,0,0}, a2 = {0,0,0,0}, a3 = {0,0,0,0};
    const float* p0 = P + (size_t)r0 * FIN;
    const float* p1 = p0 + FIN;
    const float* p2 = p1 + FIN;
    const float* p3 = p2 + FIN;

    if constexpr (FIN % 4 == 0) {
        #pragma unroll 4
        for (int k4 = 0; k4 < FIN / 4; k4++) {
            float4 x0 = __ldg((const float4*)(p0 + k4 * 4));
            float4 x1 = __ldg((const float4*)(p1 + k4 * 4));
            float4 x2 = __ldg((const float4*)(p2 + k4 * 4));
            float4 x3 = __ldg((const float4*)(p3 + k4 * 4));
            #pragma unroll
            for (int j = 0; j < 4; j++) {
                float4 wv = __ldg((const float4*)(W + (size_t)(k4 * 4 + j) * FOUT + c));
                float e0 = (j == 0) ? x0.x : (j == 1) ? x0.y : (j == 2) ? x0.z : x0.w;
                float e1 = (j == 0) ? x1.x : (j == 1) ? x1.y : (j == 2) ? x1.z : x1.w;
                float e2 = (j == 0) ? x2.x : (j == 1) ? x2.y : (j == 2) ? x2.z : x2.w;
                float e3 = (j == 0) ? x3.x : (j == 1) ? x3.y : (j == 2) ? x3.z : x3.w;
                a0.x += e0 * wv.x; a0.y += e0 * wv.y; a0.z += e0 * wv.z; a0.w += e0 * wv.w;
                a1.x += e1 * wv.x; a1.y += e1 * wv.y; a1.z += e1 * wv.z; a1.w += e1 * wv.w;
                a2.x += e2 * wv.x; a2.y += e2 * wv.y; a2.z += e2 * wv.z; a2.w += e2 * wv.w;
                a3.x += e3 * wv.x; a3.y += e3 * wv.y; a3.z += e3 * wv.z; a3.w += e3 * wv.w;
            }
        }
    } else {
        #pragma unroll
        for (int k = 0; k < FIN; k++) {
            float4 wv = __ldg((const float4*)(W + (size_t)k * FOUT + c));
            float x0 = __ldg(p0 + k), x1 = __ldg(p1 + k), x2 = __ldg(p2 + k), x3 = __ldg(p3 + k);
            a0.x += x0 * wv.x; a0.y += x0 * wv.y; a0.z += x0 * wv.z; a0.w += x0 * wv.w;
            a1.x += x1 * wv.x; a1.y += x1 * wv.y; a1.z += x1 * wv.z; a1.w += x1 * wv.w;
            a2.x += x2 * wv.x; a2.y += x2 * wv.y; a2.z += x2 * wv.z; a2.w += x2 * wv.w;
            a3.x += x3 * wv.x; a3.y += x3 * wv.y; a3.z += x3 * wv.z; a3.w += x3 * wv.w;
        }
    }

    float4 bv = __ldg((const float4*)(B + c));

    #pragma unroll
    for (int j = 0; j < 4; j++) {
        float4 a = (j == 0) ? a0 : (j == 1) ? a1 : (j == 2) ? a2 : a3;
        float m = SCALE ? g_dis[r0 + j] : 1.0f;
        float4 o;
        o.x = m * fmaxf(a.x + bv.x, 0.f);
        o.y = m * fmaxf(a.y + bv.y, 0.f);
        o.z = m * fmaxf(a.z + bv.z, 0.f);
        o.w = m * fmaxf(a.w + bv.w, 0.f);
        *(float4*)(Yo + (size_t)(r0 + j) * FOUT + c) = o;
    }
}

// ==================== pooling: warp covers 128 ch of KP serial nodes ====================
__global__ void pool_k(const float* __restrict__ X, const int* __restrict__ batch) {
    int t = blockIdx.x * blockDim.x + threadIdx.x;
    int grp = t >> 5;               // warp id
    int lane = t & 31;
    int n0 = grp * KP;
    if (n0 >= NN) return;
    int c = lane * 4;
    float4 m = {0.f, 0.f, 0.f, 0.f};
    int curb = batch[n0];
    for (int k = 0; k < KP; k++) {
        int n = n0 + k;
        int b = batch[n];
        if (b != curb) {
            unsigned* gp = g_pool + (size_t)curb * 128 + c;
            atomicMax(gp + 0, __float_as_uint(m.x));
            atomicMax(gp + 1, __float_as_uint(m.y));
            atomicMax(gp + 2, __float_as_uint(m.z));
            atomicMax(gp + 3, __float_as_uint(m.w));
            m = make_float4(0.f, 0.f, 0.f, 0.f);
            curb = b;
        }
        float4 v = *(const float4*)(X + (size_t)n * 128 + c);
        m.x = fmaxf(m.x, v.x); m.y = fmaxf(m.y, v.y);
        m.z = fmaxf(m.z, v.z); m.w = fmaxf(m.w, v.w);
    }
    unsigned* gp = g_pool + (size_t)curb * 128 + c;
    atomicMax(gp + 0, __float_as_uint(m.x));
    atomicMax(gp + 1, __float_as_uint(m.y));
    atomicMax(gp + 2, __float_as_uint(m.z));
    atomicMax(gp + 3, __float_as_uint(m.w));
}

// ==================== MLP head ====================
__global__ void mlp_k(const float* __restrict__ Wl1, const float* __restrict__ bl1,
                      const float* __restrict__ Wl2, const float* __restrict__ bl2,
                      float* __restrict__ out) {
    __shared__ float gr[128];
    __shared__ float hid[64];
    int g = blockIdx.x;
    int t = threadIdx.x;   // 64 threads
    gr[t]      = __uint_as_float(g_pool[(size_t)g * 128 + t]);
    gr[t + 64] = __uint_as_float(g_pool[(size_t)g * 128 + t + 64]);
    __syncthreads();
    float a = bl1[t];
    #pragma unroll 8
    for (int k = 0; k < 128; k++) a += gr[k] * Wl1[(size_t)k * 64 + t];
    hid[t] = fmaxf(a, 0.f);
    __syncthreads();
    if (t < 10) {
        float o = bl2[t];
        #pragma unroll 8
        for (int j = 0; j < 64; j++) o += hid[j] * Wl2[(size_t)j * 10 + t];
        out[(size_t)g * 10 + t] = o;
    }
}

// ==================== host launcher ====================
extern "C" void kernel_launch(void* const* d_in, const int* in_sizes, int n_in,
                              void* d_out, int out_size) {
    const float* x     = (const float*)d_in[0];
    const int*   ei    = (const int*)d_in[1];
    const int*   batch = (const int*)d_in[2];
    const float* W[6], *b[6];
    for (int i = 0; i < 6; i++) {
        W[i] = (const float*)d_in[3 + 2 * i];
        b[i] = (const float*)d_in[4 + 2 * i];
    }
    const float* Wl1 = (const float*)d_in[15];
    const float* bl1 = (const float*)d_in[16];
    const float* Wl2 = (const float*)d_in[17];
    const float* bl2 = (const float*)d_in[18];
    float* out = (float*)d_out;

    float *YA, *YB, *P;
    cudaGetSymbolAddress((void**)&YA, g_YA);
    cudaGetSymbolAddress((void**)&YB, g_YB);
    cudaGetSymbolAddress((void**)&P,  g_P);

    const int T = 256;

    // CSR build + degree sort + normalization
    prep_init_k<<<cdiv(NN, T), T>>>();
    hist_k<<<cdiv(EE, T), T>>>(ei);
    scan_a_k<<<NBLK, 1024>>>();
    scan_b2_k<<<2, DB>>>();
    scan_c_k<<<cdiv(NN, T), T>>>(x);
    place_k<<<cdiv(EE, T), T>>>(ei);

    // layer 1: fin=2 -> 16
    agg2_k<<<cdiv(NN, T), T>>>(YA, P);
    gemm_k<2, 16, true><<<cdiv((long long)(NN / 4) * 4, T), T>>>(P, W[0], b[0], YB);

    // layer 2: 16 -> 32
    agg_k<16><<<cdiv((long long)NN * 4, T), T>>>(YB, P);
    gemm_k<16, 32, true><<<cdiv((long long)(NN / 4) * 8, T), T>>>(P, W[1], b[1], YA);

    // layer 3: 32 -> 48
    agg_k<32><<<cdiv((long long)NN * 8, T), T>>>(YA, P);
    gemm_k<32, 48, true><<<cdiv((long long)(NN / 4) * 12, T), T>>>(P, W[2], b[2], YB);

    // layer 4: 48 -> 64
    agg_k<48><<<cdiv((long long)NN * 12, T), T>>>(YB, P);
    gemm_k<48, 64, true><<<cdiv((long long)(NN / 4) * 16, T), T>>>(P, W[3], b[3], YA);

    // layer 5: 64 -> 96
    agg_k<64><<<cdiv((long long)NN * 16, T), T>>>(YA, P);
    gemm_k<64, 96, true><<<cdiv((long long)(NN / 4) * 24, T), T>>>(P, W[4], b[4], YB);

    // layer 6: 96 -> 128 (no dis scaling: final node features)
    agg_k<96><<<cdiv((long long)NN * 24, T), T>>>(YB, P);
    gemm_k<96, 128, false><<<cdiv((long long)(NN / 4) * 32, T), T>>>(P, W[5], b[5], YA);

    // pool + head
    pool_k<<<cdiv((long long)(NN / KP) * 32, T), T>>>(YA, batch);
    mlp_k<<<GG, 64>>>(Wl1, bl1, Wl2, bl2, out);
}

// round 6
// speedup vs baseline: 2.0560x; 1.0902x over previous
#include <cuda_runtime.h>
#include <cuda_fp16.h>
#include <cstdint>

#define NN 131072
#define EE 2097152
#define GG 512
#define NBLK 128          // scan blocks: 128 * 1024 = NN
#define DB 512            // degree-histogram bins
#define KP 16             // nodes per pool warp

// -------------------- device scratch (no allocations allowed) --------------------
__device__ __half g_YA[(size_t)NN * 128];   // fp16 feature ping
__device__ __half g_YB[(size_t)NN * 128];   // fp16 feature pong
__device__ float  g_P [(size_t)NN * 128];   // fp32 aggregated (GEMM input)
__device__ float  g_X [(size_t)NN * 128];   // fp32 final-layer output
__device__ float  g_dis[NN];
__device__ int    g_cnt[NN];
__device__ int    g_rowptr[NN + 1];
__device__ int    g_bsum[NBLK];
__device__ int    g_dhist[DB];
__device__ int    g_perm[NN];
__device__ int    g_col[EE];
__device__ unsigned g_pool[GG * 128];

static inline int cdiv(long long a, int b) { return (int)((a + b - 1) / b); }

// -------------------- fp16 <-> fp32 helpers --------------------
__device__ __forceinline__ float4 h4_to_f4(uint2 u) {
    __half2 a = *reinterpret_cast<__half2*>(&u.x);
    __half2 b = *reinterpret_cast<__half2*>(&u.y);
    float2 fa = __half22float2(a), fb = __half22float2(b);
    return make_float4(fa.x, fa.y, fb.x, fb.y);
}
__device__ __forceinline__ uint2 f4_to_h4(float4 v) {
    __half2 a = __floats2half2_rn(v.x, v.y);
    __half2 b = __floats2half2_rn(v.z, v.w);
    uint2 u;
    u.x = *reinterpret_cast<unsigned*>(&a);
    u.y = *reinterpret_cast<unsigned*>(&b);
    return u;
}

// ==================== CSR build + degree sort ====================
__global__ void prep_init_k() {
    int n = blockIdx.x * blockDim.x + threadIdx.x;
    if (n < NN) g_cnt[n] = 0;
    if (n < GG * 128) g_pool[n] = 0u;
    if (n < DB) g_dhist[n] = 0;
}

__global__ void hist_k(const int* __restrict__ ei) {
    int e = blockIdx.x * blockDim.x + threadIdx.x;
    if (e >= EE) return;
    atomicAdd(&g_cnt[ei[EE + e]], 1);
}

__global__ void scan_a_k() {
    __shared__ int wsum[32];
    int n = blockIdx.x * 1024 + threadIdx.x;
    int lane = threadIdx.x & 31, wid = threadIdx.x >> 5;
    int v = g_cnt[n];
    atomicAdd(&g_dhist[v < DB ? v : DB - 1], 1);
    int x = v;
    #pragma unroll
    for (int o = 1; o < 32; o <<= 1) { int y = __shfl_up_sync(~0u, x, o); if (lane >= o) x += y; }
    if (lane == 31) wsum[wid] = x;
    __syncthreads();
    if (wid == 0) {
        int s = wsum[lane];
        #pragma unroll
        for (int o = 1; o < 32; o <<= 1) { int y = __shfl_up_sync(~0u, s, o); if (lane >= o) s += y; }
        wsum[lane] = s;
    }
    __syncthreads();
    int excl = x - v + (wid > 0 ? wsum[wid - 1] : 0);
    g_rowptr[n] = excl;
    if (threadIdx.x == 1023) g_bsum[blockIdx.x] = excl + v;
}

__device__ __forceinline__ void scan_shared(int* sh, int n, int t) {
    for (int o = 1; o < n; o <<= 1) {
        int add = (t >= o && t < n) ? sh[t - o] : 0;
        __syncthreads();
        if (t < n) sh[t] += add;
        __syncthreads();
    }
}

__global__ void scan_b2_k() {
    __shared__ int sh[DB];
    int t = threadIdx.x;               // 512 threads
    if (blockIdx.x == 0) {
        int v = (t < NBLK) ? g_bsum[t] : 0;
        if (t < NBLK) sh[t] = v;
        __syncthreads();
        scan_shared(sh, NBLK, t);
        if (t < NBLK) g_bsum[t] = sh[t] - v;
    } else {
        int v = g_dhist[t];
        sh[t] = v;
        __syncthreads();
        scan_shared(sh, DB, t);
        g_dhist[t] = sh[t] - v;
    }
}

__global__ void scan_c_k(const float* __restrict__ x) {
    int n = blockIdx.x * blockDim.x + threadIdx.x;
    if (n >= NN) return;
    g_rowptr[n] += g_bsum[n >> 10];
    int deg = g_cnt[n];
    float dv = rsqrtf((float)deg + 1.0f);
    g_dis[n] = dv;
    int d = deg < DB ? deg : DB - 1;
    int p = atomicAdd(&g_dhist[d], 1);
    g_perm[p] = n;
    g_cnt[n] = 0;
    ((__half2*)g_YA)[n] = __floats2half2_rn(dv * x[2 * n], dv * x[2 * n + 1]);
    if (n == 0) g_rowptr[NN] = EE;
}

__global__ void place_k(const int* __restrict__ ei) {
    int e = blockIdx.x * blockDim.x + threadIdx.x;
    if (e >= EE) return;
    int s = ei[e];
    int d = ei[EE + e];
    int p = atomicAdd(&g_cnt[d], 1);
    g_col[g_rowptr[d] + p] = s;
}

// ==================== aggregation: P_i = dis_i * (Y_i + sum_{j in N(i)} Y_j) ====================
template<int FIN>
__global__ void agg_k(const __half* __restrict__ Y, float* __restrict__ P) {
    constexpr int G = FIN / 4;
    long long t = (long long)blockIdx.x * blockDim.x + threadIdx.x;
    int grp = (int)(t / G);
    int c = (int)(t % G) * 4;
    if (grp >= NN) return;
    int node = g_perm[grp];
    int beg = g_rowptr[node], end = g_rowptr[node + 1];
    float4 acc = h4_to_f4(__ldg((const uint2*)(Y + (size_t)node * FIN + c)));  // self
    int i = beg;
    for (; i + 4 <= end; i += 4) {
        int j0 = g_col[i], j1 = g_col[i + 1], j2 = g_col[i + 2], j3 = g_col[i + 3];
        float4 v0 = h4_to_f4(__ldg((const uint2*)(Y + (size_t)j0 * FIN + c)));
        float4 v1 = h4_to_f4(__ldg((const uint2*)(Y + (size_t)j1 * FIN + c)));
        float4 v2 = h4_to_f4(__ldg((const uint2*)(Y + (size_t)j2 * FIN + c)));
        float4 v3 = h4_to_f4(__ldg((const uint2*)(Y + (size_t)j3 * FIN + c)));
        acc.x += (v0.x + v1.x) + (v2.x + v3.x);
        acc.y += (v0.y + v1.y) + (v2.y + v3.y);
        acc.z += (v0.z + v1.z) + (v2.z + v3.z);
        acc.w += (v0.w + v1.w) + (v2.w + v3.w);
    }
    for (; i < end; i++) {
        int j = g_col[i];
        float4 v = h4_to_f4(__ldg((const uint2*)(Y + (size_t)j * FIN + c)));
        acc.x += v.x; acc.y += v.y; acc.z += v.z; acc.w += v.w;
    }
    float s = g_dis[node];
    acc.x *= s; acc.y *= s; acc.z *= s; acc.w *= s;
    *(float4*)(P + (size_t)node * FIN + c) = acc;
}

// FIN=2: one thread per node, half2 loads
__global__ void agg2_k(const __half* __restrict__ Y, float* __restrict__ P) {
    int grp = blockIdx.x * blockDim.x + threadIdx.x;
    if (grp >= NN) return;
    int node = g_perm[grp];
    int beg = g_rowptr[node], end = g_rowptr[node + 1];
    float2 acc = __half22float2(__ldg((const __half2*)Y + node));
    int i = beg;
    for (; i + 4 <= end; i += 4) {
        int j0 = g_col[i], j1 = g_col[i + 1], j2 = g_col[i + 2], j3 = g_col[i + 3];
        float2 v0 = __half22float2(__ldg((const __half2*)Y + j0));
        float2 v1 = __half22float2(__ldg((const __half2*)Y + j1));
        float2 v2 = __half22float2(__ldg((const __half2*)Y + j2));
        float2 v3 = __half22float2(__ldg((const __half2*)Y + j3));
        acc.x += (v0.x + v1.x) + (v2.x + v3.x);
        acc.y += (v0.y + v1.y) + (v2.y + v3.y);
    }
    for (; i < end; i++) {
        float2 v = __half22float2(__ldg((const __half2*)Y + g_col[i]));
        acc.x += v.x; acc.y += v.y;
    }
    float s = g_dis[node];
    acc.x *= s; acc.y *= s;
    *(float2*)(P + (size_t)node * 2) = acc;
}

// ==================== GEMM + bias + relu (+ dis scaling), half or float output ====================
template<int FIN, int FOUT, bool SCALE, bool HOUT>
__global__ void gemm_k(const float* __restrict__ P, const float* __restrict__ W,
                       const float* __restrict__ B, void* __restrict__ Yo_) {
    constexpr int TPR = FOUT / 4;
    int t = blockIdx.x * blockDim.x + threadIdx.x;
    int rg = t / TPR;
    int c = (t % TPR) * 4;
    int r0 = rg * 4;
    if (r0 >= NN) return;

    float4 a0 = {0,0,0,0}, a1 = {0,0,0,0}, a2 = {0,0,0,0}, a3 = {0,0,0,0};
    const float* p0 = P + (size_t)r0 * FIN;
    const float* p1 = p0 + FIN;
    const float* p2 = p1 + FIN;
    const float* p3 = p2 + FIN;

    if constexpr (FIN % 4 == 0) {
        #pragma unroll 4
        for (int k4 = 0; k4 < FIN / 4; k4++) {
            float4 x0 = __ldg((const float4*)(p0 + k4 * 4));
            float4 x1 = __ldg((const float4*)(p1 + k4 * 4));
            float4 x2 = __ldg((const float4*)(p2 + k4 * 4));
            float4 x3 = __ldg((const float4*)(p3 + k4 * 4));
            #pragma unroll
            for (int j = 0; j < 4; j++) {
                float4 wv = __ldg((const float4*)(W + (size_t)(k4 * 4 + j) * FOUT + c));
                float e0 = (j == 0) ? x0.x : (j == 1) ? x0.y : (j == 2) ? x0.z : x0.w;
                float e1 = (j == 0) ? x1.x : (j == 1) ? x1.y : (j == 2) ? x1.z : x1.w;
                float e2 = (j == 0) ? x2.x : (j == 1) ? x2.y : (j == 2) ? x2.z : x2.w;
                float e3 = (j == 0) ? x3.x : (j == 1) ? x3.y : (j == 2) ? x3.z : x3.w;
                a0.x += e0 * wv.x; a0.y += e0 * wv.y; a0.z += e0 * wv.z; a0.w += e0 * wv.w;
                a1.x += e1 * wv.x; a1.y += e1 * wv.y; a1.z += e1 * wv.z; a1.w += e1 * wv.w;
                a2.x += e2 * wv.x; a2.y += e2 * wv.y; a2.z += e2 * wv.z; a2.w += e2 * wv.w;
                a3.x += e3 * wv.x; a3.y += e3 * wv.y; a3.z += e3 * wv.z; a3.w += e3 * wv.w;
            }
        }
    } else {
        #pragma unroll
        for (int k = 0; k < FIN; k++) {
            float4 wv = __ldg((const float4*)(W + (size_t)k * FOUT + c));
            float x0 = __ldg(p0 + k), x1 = __ldg(p1 + k), x2 = __ldg(p2 + k), x3 = __ldg(p3 + k);
            a0.x += x0 * wv.x; a0.y += x0 * wv.y; a0.z += x0 * wv.z; a0.w += x0 * wv.w;
            a1.x += x1 * wv.x; a1.y += x1 * wv.y; a1.z += x1 * wv.z; a1.w += x1 * wv.w;
            a2.x += x2 * wv.x; a2.y += x2 * wv.y; a2.z += x2 * wv.z; a2.w += x2 * wv.w;
            a3.x += x3 * wv.x; a3.y += x3 * wv.y; a3.z += x3 * wv.z; a3.w += x3 * wv.w;
        }
    }

    float4 bv = __ldg((const float4*)(B + c));

    #pragma unroll
    for (int j = 0; j < 4; j++) {
        float4 a = (j == 0) ? a0 : (j == 1) ? a1 : (j == 2) ? a2 : a3;
        float m = SCALE ? g_dis[r0 + j] : 1.0f;
        float4 o;
        o.x = m * fmaxf(a.x + bv.x, 0.f);
        o.y = m * fmaxf(a.y + bv.y, 0.f);
        o.z = m * fmaxf(a.z + bv.z, 0.f);
        o.w = m * fmaxf(a.w + bv.w, 0.f);
        if constexpr (HOUT) {
            __half* Yo = (__half*)Yo_;
            *(uint2*)(Yo + (size_t)(r0 + j) * FOUT + c) = f4_to_h4(o);
        } else {
            float* Yo = (float*)Yo_;
            *(float4*)(Yo + (size_t)(r0 + j) * FOUT + c) = o;
        }
    }
}

// ==================== pooling: warp covers 128 ch of KP serial nodes ====================
__global__ void pool_k(const float* __restrict__ X, const int* __restrict__ batch) {
    int t = blockIdx.x * blockDim.x + threadIdx.x;
    int grp = t >> 5;
    int lane = t & 31;
    int n0 = grp * KP;
    if (n0 >= NN) return;
    int c = lane * 4;
    float4 m = {0.f, 0.f, 0.f, 0.f};
    int curb = batch[n0];
    for (int k = 0; k < KP; k++) {
        int n = n0 + k;
        int b = batch[n];
        if (b != curb) {
            unsigned* gp = g_pool + (size_t)curb * 128 + c;
            atomicMax(gp + 0, __float_as_uint(m.x));
            atomicMax(gp + 1, __float_as_uint(m.y));
            atomicMax(gp + 2, __float_as_uint(m.z));
            atomicMax(gp + 3, __float_as_uint(m.w));
            m = make_float4(0.f, 0.f, 0.f, 0.f);
            curb = b;
        }
        float4 v = *(const float4*)(X + (size_t)n * 128 + c);
        m.x = fmaxf(m.x, v.x); m.y = fmaxf(m.y, v.y);
        m.z = fmaxf(m.z, v.z); m.w = fmaxf(m.w, v.w);
    }
    unsigned* gp = g_pool + (size_t)curb * 128 + c;
    atomicMax(gp + 0, __float_as_uint(m.x));
    atomicMax(gp + 1, __float_as_uint(m.y));
    atomicMax(gp + 2, __float_as_uint(m.z));
    atomicMax(gp + 3, __float_as_uint(m.w));
}

// ==================== MLP head ====================
__global__ void mlp_k(const float* __restrict__ Wl1, const float* __restrict__ bl1,
                      const float* __restrict__ Wl2, const float* __restrict__ bl2,
                      float* __restrict__ out) {
    __shared__ float gr[128];
    __shared__ float hid[64];
    int g = blockIdx.x;
    int t = threadIdx.x;   // 64 threads
    gr[t]      = __uint_as_float(g_pool[(size_t)g * 128 + t]);
    gr[t + 64] = __uint_as_float(g_pool[(size_t)g * 128 + t + 64]);
    __syncthreads();
    float a = bl1[t];
    #pragma unroll 8
    for (int k = 0; k < 128; k++) a += gr[k] * Wl1[(size_t)k * 64 + t];
    hid[t] = fmaxf(a, 0.f);
    __syncthreads();
    if (t < 10) {
        float o = bl2[t];
        #pragma unroll 8
        for (int j = 0; j < 64; j++) o += hid[j] * Wl2[(size_t)j * 10 + t];
        out[(size_t)g * 10 + t] = o;
    }
}

// ==================== host launcher ====================
extern "C" void kernel_launch(void* const* d_in, const int* in_sizes, int n_in,
                              void* d_out, int out_size) {
    const float* x     = (const float*)d_in[0];
    const int*   ei    = (const int*)d_in[1];
    const int*   batch = (const int*)d_in[2];
    const float* W[6], *b[6];
    for (int i = 0; i < 6; i++) {
        W[i] = (const float*)d_in[3 + 2 * i];
        b[i] = (const float*)d_in[4 + 2 * i];
    }
    const float* Wl1 = (const float*)d_in[15];
    const float* bl1 = (const float*)d_in[16];
    const float* Wl2 = (const float*)d_in[17];
    const float* bl2 = (const float*)d_in[18];
    float* out = (float*)d_out;

    __half *YA, *YB;
    float *P, *X;
    cudaGetSymbolAddress((void**)&YA, g_YA);
    cudaGetSymbolAddress((void**)&YB, g_YB);
    cudaGetSymbolAddress((void**)&P,  g_P);
    cudaGetSymbolAddress((void**)&X,  g_X);

    const int T = 256;

    // CSR build + degree sort + normalization
    prep_init_k<<<cdiv(NN, T), T>>>();
    hist_k<<<cdiv(EE, T), T>>>(ei);
    scan_a_k<<<NBLK, 1024>>>();
    scan_b2_k<<<2, DB>>>();
    scan_c_k<<<cdiv(NN, T), T>>>(x);
    place_k<<<cdiv(EE, T), T>>>(ei);

    // layer 1: fin=2 -> 16
    agg2_k<<<cdiv(NN, T), T>>>(YA, P);
    gemm_k<2, 16, true, true><<<cdiv((long long)(NN / 4) * 4, T), T>>>(P, W[0], b[0], YB);

    // layer 2: 16 -> 32
    agg_k<16><<<cdiv((long long)NN * 4, T), T>>>(YB, P);
    gemm_k<16, 32, true, true><<<cdiv((long long)(NN / 4) * 8, T), T>>>(P, W[1], b[1], YA);

    // layer 3: 32 -> 48
    agg_k<32><<<cdiv((long long)NN * 8, T), T>>>(YA, P);
    gemm_k<32, 48, true, true><<<cdiv((long long)(NN / 4) * 12, T), T>>>(P, W[2], b[2], YB);

    // layer 4: 48 -> 64
    agg_k<48><<<cdiv((long long)NN * 12, T), T>>>(YB, P);
    gemm_k<48, 64, true, true><<<cdiv((long long)(NN / 4) * 16, T), T>>>(P, W[3], b[3], YA);

    // layer 5: 64 -> 96
    agg_k<64><<<cdiv((long long)NN * 16, T), T>>>(YA, P);
    gemm_k<64, 96, true, true><<<cdiv((long long)(NN / 4) * 24, T), T>>>(P, W[4], b[4], YB);

    // layer 6: 96 -> 128 (fp32 output, no dis scaling)
    agg_k<96><<<cdiv((long long)NN * 24, T), T>>>(YB, P);
    gemm_k<96, 128, false, false><<<cdiv((long long)(NN / 4) * 32, T), T>>>(P, W[5], b[5], X);

    // pool + head
    pool_k<<<cdiv((long long)(NN / KP) * 32, T), T>>>(X, batch);
    mlp_k<<<GG, 64>>>(Wl1, bl1, Wl2, bl2, out);
}